// round 14
// baseline (speedup 1.0000x reference)
#include <cuda_runtime.h>
#include <math.h>

#define BSZ    65536
#define TT     31
#define HIDN   128
#define NVOCAB 19
#define NCONST 40
#define INSZ   133
#define SLOTS  96
#define NTH    640
#define NW     20
#define NBLK   152

#define OUT_CV  2031616   // BSZ*TT
#define OUT_LP  4063232   // 2*BSZ*TT
#define OUT_TOT 4194304

typedef unsigned long long u64;

// shared float layout
#define S_WHH  0            // float4[kq=32][j=128]
#define S_TOKP 16384        // float4[kq=32][v=32]
#define S_CON  20480        // [k][64]
#define S_H    28672        // [96][128]
#define S_ACC  40960        // [96][128]
#define S_WX   53248        // [f=9][j=128]
#define S_BSUM 54400
#define S_BTOK 54528
#define S_BCON 54560
#define S_LP   54624        // 96
#define S_NF   54720
// int region
#define SI_POS  0
#define SI_SP   96
#define SI_ACT  192
#define SI_T    288
#define SI_GROW 384
#define SI_STK  480         // 96 x 8
#define SI_LIST 1248        // 96
#define SI_DEAD 1344        // 96
#define SI_CNT  1440        // [0]=A [1]=navail [2]=base [3]=oldc
#define SI_N    1444
#define SMEM_BYTES ((S_NF + SI_N) * 4)

#define FULLM 0xffffffffu

__device__ float g_WihT[INSZ * HIDN];   // [c][j]
__device__ int   g_next;

__device__ __forceinline__ u64 ffma2(u64 a, u64 b, u64 c) {
    u64 d;
    asm("fma.rn.f32x2 %0, %1, %2, %3;" : "=l"(d) : "l"(a), "l"(b), "l"(c));
    return d;
}
__device__ __forceinline__ float f2lo(u64 v) { return __uint_as_float((unsigned)v); }
__device__ __forceinline__ float f2hi(u64 v) { return __uint_as_float((unsigned)(v >> 32)); }

__device__ __forceinline__ void lds2(u64& a, u64& b, const float* p) {
    unsigned addr = (unsigned)__cvta_generic_to_shared(p);
    asm("ld.shared.v2.b64 {%0, %1}, [%2];" : "=l"(a), "=l"(b) : "r"(addr));
}

// warp max of f32 via order-preserving s32 map + redux.sync.max.s32 (sm_80+).
__device__ __forceinline__ float rmaxf(float v) {
    int b = __float_as_int(v);
    int k = b ^ ((b >> 31) & 0x7FFFFFFF);
    int r;
    asm("redux.sync.max.s32 %0, %1, 0xffffffff;" : "=r"(r) : "r"(k));
    return __int_as_float(r ^ ((r >> 31) & 0x7FFFFFFF));
}
// warp sum via fixed-point redux.add.s32; SCALE chosen so no overflow.
__device__ __forceinline__ float rsumf(float v, float scale, float inv_scale) {
    int fx = (int)(v * scale);
    int r;
    asm("redux.sync.add.s32 %0, %1, 0xffffffff;" : "=r"(r) : "r"(fx));
    return (float)r * inv_scale;
}

__device__ __forceinline__ float gumbelf(float u) {
    float inner = -logf(u + 1e-9f);
    return -logf(inner + 1e-9f);
}

// GEMV + tanh + h-store for CNT rows (CNT in {2,4}); duplicate rows within one
// call are idempotent (all reads precede all writes).
template<int CNT>
__device__ __forceinline__ void phaseA(float* sm, const int* grp, int lane)
{
    u64 zp[CNT][4];
#pragma unroll
    for (int i = 0; i < CNT; i++)
#pragma unroll
        for (int m = 0; m < 4; m++) zp[i][m] = 0ull;
#pragma unroll 4
    for (int kq = 0; kq < 32; kq++) {
        u64 h01[CNT], h23[CNT];
#pragma unroll
        for (int i = 0; i < CNT; i++)
            lds2(h01[i], h23[i], sm + S_H + grp[i] * HIDN + 4 * kq);
#pragma unroll
        for (int m = 0; m < 4; m++) {
            u64 w01, w23;
            lds2(w01, w23, sm + S_WHH + (kq * 128 + lane + 32 * m) * 4);
#pragma unroll
            for (int i = 0; i < CNT; i++) {
                zp[i][m] = ffma2(h01[i], w01, zp[i][m]);
                zp[i][m] = ffma2(h23[i], w23, zp[i][m]);
            }
        }
    }
    float hnew[CNT][4];
#pragma unroll
    for (int i = 0; i < CNT; i++)
#pragma unroll
        for (int m = 0; m < 4; m++) {
            int j = lane + 32 * m;
            float z = f2lo(zp[i][m]) + f2hi(zp[i][m]);
            float a = sm[S_ACC + grp[i] * HIDN + j];
            hnew[i][m] = tanhf(z + a);
        }
    __syncwarp();
#pragma unroll
    for (int i = 0; i < CNT; i++)
#pragma unroll
        for (int m = 0; m < 4; m++)
            sm[S_H + grp[i] * HIDN + lane + 32 * m] = hnew[i][m];
    __syncwarp();
}

// One decode super-step for up to N rows (real count rcnt <= N; slots beyond
// rcnt duplicate grp[0], gated out of all state writes). nold = count of
// non-fresh rows (prefix) needing the recurrent GEMV. Returns survivor mask.
template<int N>
__device__ __forceinline__ unsigned superstep(float* sm, int* si,
                           const float* __restrict__ noise_tok,
                           const float* __restrict__ noise_c,
                           float* __restrict__ out,
                           const int* grp, int rcnt, int nold, int lane)
{
    int p[N], tt[N], gr[N];
    float g_t[N];
#pragma unroll
    for (int i = 0; i < N; i++) {
        int row = grp[i];
        p[i]  = si[SI_POS + row];
        tt[i] = si[SI_T + row];
        gr[i] = si[SI_GROW + row];
        long long bt = (long long)tt[i] * BSZ + gr[i];
        float u = (lane < NVOCAB) ? __ldg(&noise_tok[bt * NVOCAB + lane]) : 0.5f;
        g_t[i] = gumbelf(u);   // overlaps GEMV below
    }

    // Phase A on the old prefix, in sub-calls of 4/2 with in-call duplicate pad
    if (nold > 0) {
        if (N >= 5 && nold >= 5) {
            { int g4[4] = { grp[0], grp[1], grp[2], grp[3] }; phaseA<4>(sm, g4, lane); }
            if (nold == 6) { int g2[2] = { grp[4], grp[5] }; phaseA<2>(sm, g2, lane); }
            else           { int g2[2] = { grp[4], grp[4] }; phaseA<2>(sm, g2, lane); }
        } else if (N >= 3 && nold >= 3) {
            if (nold >= 4) { int g4[4] = { grp[0], grp[1], grp[2], grp[3] }; phaseA<4>(sm, g4, lane); }
            else           { int g4[4] = { grp[0], grp[1], grp[2], grp[0] }; phaseA<4>(sm, g4, lane); }
        } else {
            if (nold == 2) { int g2[2] = { grp[0], grp[1] }; phaseA<2>(sm, g2, lane); }
            else           { int g2[2] = { grp[0], grp[0] }; phaseA<2>(sm, g2, lane); }
        }
    }

    // Phase B: token head logits (lane = vocab index), N-way amortized
    u64 tkp[N];
#pragma unroll
    for (int i = 0; i < N; i++) tkp[i] = 0ull;
#pragma unroll 4
    for (int kq = 0; kq < 32; kq++) {
        u64 w01, w23;
        lds2(w01, w23, sm + S_TOKP + (kq * 32 + lane) * 4);
#pragma unroll
        for (int i = 0; i < N; i++) {
            u64 h01, h23;
            lds2(h01, h23, sm + S_H + grp[i] * HIDN + 4 * kq);
            tkp[i] = ffma2(h01, w01, tkp[i]);
            tkp[i] = ffma2(h23, w23, tkp[i]);
        }
    }
    float btok = sm[S_BTOK + lane];
    const float NEGINF = -INFINITY;

    // Phase C1: batched softmax + Gumbel argmax (redux-based, 1-round reductions)
    float ltok[N];
#pragma unroll
    for (int i = 0; i < N; i++) {
        float l = NEGINF;
        if (lane < NVOCAB) {
            l = f2lo(tkp[i]) + f2hi(tkp[i]) + btok;
            if (p[i] >= 15 && lane < 6) l = NEGINF;
        }
        ltok[i] = l;
    }
    float mx[N];
#pragma unroll
    for (int i = 0; i < N; i++) mx[i] = rmaxf(ltok[i]);
    float sme[N];
#pragma unroll
    for (int i = 0; i < N; i++)
        sme[i] = (lane < NVOCAB) ? expf(ltok[i] - mx[i]) : 0.f;
    float ssum[N];
#pragma unroll
    for (int i = 0; i < N; i++)
        ssum[i] = rsumf(sme[i], 33554432.0f, 2.9802322387695312e-8f);
    float lpt[N], sc[N];
#pragma unroll
    for (int i = 0; i < N; i++) {
        float lse = logf(ssum[i]);
        lpt[i] = ltok[i] - mx[i] - lse;
        sc[i]  = lpt[i] + g_t[i];
    }
    float scm[N];
#pragma unroll
    for (int i = 0; i < N; i++) scm[i] = rmaxf(sc[i]);
    int ci[N];
    float lpw[N];
#pragma unroll
    for (int i = 0; i < N; i++) {
        unsigned b = __ballot_sync(FULLM, sc[i] == scm[i]);
        int widx = __ffs(b) - 1;        // first (lowest-index) max = jnp.argmax
        ci[i]  = widx;
        lpw[i] = __shfl_sync(FULLM, lpt[i], widx);
    }

    // Phase C2: rare const head + bookkeeping (only real rows)
    unsigned alive = 0;
#pragma unroll
    for (int i = 0; i < N; i++) {
        if (i >= rcnt) break;
        int row = grp[i];
        int pi  = p[i];
        int choice = ci[i];
        float lp_tok = lpw[i];

        bool is_const = (choice == 18);
        float lp_c = 0.f; int cchoice = 0;
        if (is_const) {   // warp-uniform
            float2 co = make_float2(0.f, 0.f);
#pragma unroll 8
            for (int k4 = 0; k4 < 32; k4++) {
                float4 hv = *(const float4*)(sm + S_H + row * HIDN + 4 * k4);
#pragma unroll
                for (int b = 0; b < 4; b++) {
                    float2 wc = *(const float2*)(sm + S_CON + (4 * k4 + b) * 64 + 2 * lane);
                    float hk = (b == 0) ? hv.x : (b == 1) ? hv.y : (b == 2) ? hv.z : hv.w;
                    co.x = fmaf(hk, wc.x, co.x);
                    co.y = fmaf(hk, wc.y, co.y);
                }
            }
            long long bt = (long long)tt[i] * BSZ + gr[i];
            float2 uc = make_float2(0.f, 0.f);
            if (lane < 20) uc = *(const float2*)(&noise_c[bt * NCONST + 2 * lane]);
            float bc0 = sm[S_BCON + 2 * lane];
            float bc1 = sm[S_BCON + 2 * lane + 1];
            float la = (lane < 20) ? (co.x + bc0) : NEGINF;
            float lb = (lane < 20) ? (co.y + bc1) : NEGINF;
            float mc   = rmaxf(fmaxf(la, lb));
            float ec   = (lane < 20) ? (expf(la - mc) + expf(lb - mc)) : 0.f;
            float esum = rsumf(ec, 16777216.0f, 5.9604644775390625e-8f);
            float lsec = logf(esum);
            float lpa = la - mc - lsec;
            float lpb = lb - mc - lsec;
            float sa = lpa + gumbelf(uc.x);
            float sb = lpb + gumbelf(uc.y);
            float s_l, lp_l; int i_l;
            if (sb > sa) { s_l = sb; i_l = 2 * lane + 1; lp_l = lpb; }
            else         { s_l = sa; i_l = 2 * lane;     lp_l = lpa; }
            float m2 = rmaxf(s_l);
            unsigned b2 = __ballot_sync(FULLM, s_l == m2);
            int wl = __ffs(b2) - 1;     // lowest lane among maxes = lowest index
            cchoice = __shfl_sync(FULLM, i_l, wl);
            lp_c    = __shfl_sync(FULLM, lp_l, wl);
        }

        if (lane == 0) {
            float lpn = sm[S_LP + row] + lp_tok + (is_const ? lp_c : 0.f);
            out[gr[i] * TT + pi] = (float)choice;
            if (is_const) out[OUT_CV + gr[i] * TT + pi] = -10.f + 0.5f * (float)cchoice;
            int arity = (choice < 4) ? 2 : ((choice < 6) ? 1 : 0);
            int sp = si[SI_SP + row];
            if (arity == 2) {
                int wsp = sp < 7 ? sp : 7;
                si[SI_STK + row * 8 + wsp] = 2 * pi + 2;
            }
            int sp1 = sp + (arity == 2 ? 1 : 0);
            int nxt, sp2;
            if (arity != 0) { nxt = 2 * pi + 1; sp2 = sp1; }
            else {
                int ridx = sp1 - 1; if (ridx < 0) ridx = 0; if (ridx > 7) ridx = 7;
                nxt = (sp1 > 0) ? si[SI_STK + row * 8 + ridx] : -1;
                sp2 = (sp1 > 0) ? sp1 - 1 : 0;
            }
            if (nxt > TT - 1) nxt = -1;
            if (nxt >= 0) {
                alive |= (1u << i);
                sm[S_LP + row]   = lpn;
                si[SI_POS + row] = nxt;
                si[SI_SP + row]  = sp2;
                si[SI_T + row]   = tt[i] + 1;
            } else {
                si[SI_ACT + row] = 0;
                out[OUT_LP + gr[i]] = lpn;
            }
        }
        if (choice & 15) {
            int cb = 4 * pi;
#pragma unroll
            for (int m = 0; m < 4; m++) {
                int j = lane + 32 * m;
                float a = sm[S_ACC + row * HIDN + j];
#pragma unroll
                for (int b = 0; b < 4; b++)
                    if (choice & (1 << b))
                        a += __ldg(&g_WihT[(cb + b) * HIDN + j]);
                sm[S_ACC + row * HIDN + j] = a;
            }
        }
    }
    alive = __shfl_sync(FULLM, alive, 0);
    __syncwarp();
    return alive;
}

__device__ __forceinline__ unsigned run_n(int n, int nol, float* sm, int* si,
        const float* nt, const float* nc, float* out, const int* grp, int lane)
{
    if (n > 4)      return superstep<6>(sm, si, nt, nc, out, grp, n, nol, lane);
    else if (n > 2) return superstep<4>(sm, si, nt, nc, out, grp, n, nol, lane);
    else            return superstep<2>(sm, si, nt, nc, out, grp, n, nol, lane);
}

__global__ void __launch_bounds__(NTH, 1)
rnn_main(const float* __restrict__ x,
         const float* __restrict__ noise_tok,
         const float* __restrict__ noise_c,
         const float* __restrict__ W_ih,
         const float* __restrict__ W_hh,
         const float* __restrict__ b_ih,
         const float* __restrict__ b_hh,
         const float* __restrict__ W_out,
         const float* __restrict__ b_out,
         const float* __restrict__ W_c,
         const float* __restrict__ b_c,
         float* __restrict__ out)
{
    extern __shared__ float sm[];
    int* si = (int*)(sm + S_NF);
    int tid = threadIdx.x;
    int w = tid >> 5, lane = tid & 31;

    // ---- stage weights ----
    {
        const float4* src = (const float4*)W_hh;   // [j][32]
        float4* dst = (float4*)(sm + S_WHH);
        for (int idx = tid; idx < 32 * 128; idx += NTH) {
            int kq = idx >> 7, j = idx & 127;
            dst[kq * 128 + j] = src[j * 32 + kq];
        }
    }
    {
        float4* dst = (float4*)(sm + S_TOKP);
        const float4 z4 = make_float4(0.f, 0.f, 0.f, 0.f);
        const float4* src = (const float4*)W_out;  // [v][32]
        for (int idx = tid; idx < 32 * 32; idx += NTH) {
            int kq = idx >> 5, v = idx & 31;
            dst[kq * 32 + v] = (v < NVOCAB) ? src[v * 32 + kq] : z4;
        }
    }
    for (int idx = tid; idx < HIDN * 64; idx += NTH) sm[S_CON + idx] = 0.f;
    __syncthreads();
    for (int idx = tid; idx < NCONST * HIDN; idx += NTH) {
        int c = idx / HIDN, k = idx % HIDN;
        sm[S_CON + k * 64 + c] = W_c[idx];
    }
    for (int idx = tid; idx < 9 * HIDN; idx += NTH) {
        int f = idx >> 7, j = idx & 127;
        sm[S_WX + f * 128 + j] = W_ih[j * INSZ + 124 + f];
    }
    if (tid < HIDN) sm[S_BSUM + tid] = b_ih[tid] + b_hh[tid];
    if (tid < 32) sm[S_BTOK + tid] = (tid < NVOCAB) ? b_out[tid] : 0.f;
    if (tid < 64) sm[S_BCON + tid] = (tid < NCONST) ? b_c[tid] : 0.f;
    if (tid < SLOTS) si[SI_ACT + tid] = 0;
    __syncthreads();

    // ---- persistent work loop (2 barriers per round) ----
    for (;;) {
        if (w == 0) {
            unsigned lt = (1u << lane) - 1u;
            int nold = 0, ndead = 0;
            unsigned am[3];
            int po[3], pd[3];
#pragma unroll
            for (int c = 0; c < 3; c++) {
                int act = si[SI_ACT + 32 * c + lane];
                unsigned m = __ballot_sync(FULLM, act != 0);
                am[c] = m; po[c] = nold; pd[c] = ndead;
                nold  += __popc(m);
                ndead += 32 - __popc(m);
            }
            int base = 0;
            if (lane == 0 && ndead > 0) base = atomicAdd(&g_next, ndead);
            base = __shfl_sync(FULLM, base, 0);
            int navail = BSZ - base;
            if (navail < 0) navail = 0;
            if (navail > ndead) navail = ndead;
#pragma unroll
            for (int c = 0; c < 3; c++) {
                int slot = 32 * c + lane;
                if ((am[c] >> lane) & 1) si[SI_LIST + po[c] + __popc(am[c] & lt)] = slot;
                else                     si[SI_DEAD + pd[c] + __popc(~am[c] & lt)] = slot;
            }
            __syncwarp();
            for (int q = lane; q < navail; q += 32)
                si[SI_LIST + nold + q] = si[SI_DEAD + q];
            if (lane == 0) {
                si[SI_CNT]     = nold + navail;
                si[SI_CNT + 1] = navail;
                si[SI_CNT + 2] = (ndead > 0) ? base : 0;
                si[SI_CNT + 3] = nold;
            }
        }
        __syncthreads();
        int A = si[SI_CNT];
        int navail = si[SI_CNT + 1];
        int rbase  = si[SI_CNT + 2];
        int oldc   = si[SI_CNT + 3];
        if (A == 0) break;
        bool drain = (navail == 0) && (rbase >= BSZ);   // pool empty forever

        // this warp's contiguous chunk of the active list
        int lo = (A * w) / NW;
        int hi = (A * (w + 1)) / NW;

        // owner-refill: init this warp's fresh rows (h = tanh(acc); step-0 GEMV = 0)
        int fstart = lo > oldc ? lo : oldc;
        for (int idx = fstart; idx < hi; idx++) {
            int slot = si[SI_LIST + idx];
            int gr = rbase + (idx - oldc);
            float xv[9];
#pragma unroll
            for (int f = 0; f < 9; f++) xv[f] = __ldg(&x[gr * 9 + f]);
#pragma unroll
            for (int m = 0; m < 4; m++) {
                int j = lane + 32 * m;
                float a = sm[S_BSUM + j];
#pragma unroll
                for (int f = 0; f < 9; f++) a = fmaf(xv[f], sm[S_WX + f * 128 + j], a);
                sm[S_ACC + slot * HIDN + j] = a;
                sm[S_H + slot * HIDN + j] = tanhf(a);
            }
            // default-init this row's output slice (each row refilled exactly once)
            if (lane < TT) {
                out[gr * TT + lane] = -1.f;
                out[OUT_CV + gr * TT + lane] = 0.f;
            }
            if (lane == 0) {
                si[SI_POS + slot]  = 0;
                si[SI_SP + slot]   = 0;
                si[SI_T + slot]    = 0;
                si[SI_ACT + slot]  = 1;
                si[SI_GROW + slot] = gr;
                sm[S_LP + slot]    = 0.f;
            }
        }
        __syncwarp();

        // super-steps of up to 6 rows
        for (int base = lo; base < hi; base += 6) {
            int n = hi - base; if (n > 6) n = 6;
            int grp[6];
#pragma unroll
            for (int q = 0; q < 6; q++)
                grp[q] = si[SI_LIST + base + (q < n ? q : 0)];
            int nol = oldc - base;
            if (nol < 0) nol = 0;
            if (nol > n) nol = n;
            unsigned mv = run_n(n, nol, sm, si, noise_tok, noise_c, out, grp, lane);

            // drain mode: run this chunk's survivors to completion, no barriers
            while (drain && mv) {
                int ag[6]; int cnt = 0;
                for (int q = 0; q < n; q++)
                    if ((mv >> q) & 1) ag[cnt++] = grp[q];
                n = cnt;
                for (int q = 0; q < 6; q++) grp[q] = ag[q < n ? q : 0];
                mv = run_n(n, n, sm, si, noise_tok, noise_c, out, grp, lane);
            }
        }
        __syncthreads();
        if (drain) break;   // all remaining rows ran to completion above
    }
}

// prep only (out-init handled per-row at refill time)
__global__ void setup_kernel(const float* __restrict__ W_ih)
{
    int i = blockIdx.x * blockDim.x + threadIdx.x;
    if (i == 0) g_next = 0;
    if (i < INSZ * HIDN) {
        int c = i / HIDN, j = i % HIDN;
        g_WihT[c * HIDN + j] = W_ih[j * INSZ + c];
    }
}

extern "C" void kernel_launch(void* const* d_in, const int* in_sizes, int n_in,
                              void* d_out, int out_size)
{
    const float* x    = (const float*)d_in[0];
    const float* nt   = (const float*)d_in[1];
    const float* nc   = (const float*)d_in[2];
    const float* wih  = (const float*)d_in[3];
    const float* whh  = (const float*)d_in[4];
    const float* bih  = (const float*)d_in[5];
    const float* bhh  = (const float*)d_in[6];
    const float* wout = (const float*)d_in[7];
    const float* bout = (const float*)d_in[8];
    const float* wc   = (const float*)d_in[9];
    const float* bc   = (const float*)d_in[10];
    float* out = (float*)d_out;

    cudaFuncSetAttribute((const void*)rnn_main,
                         cudaFuncAttributeMaxDynamicSharedMemorySize, SMEM_BYTES);
    setup_kernel<<<(INSZ * HIDN + 255) / 256, 256>>>(wih);
    rnn_main<<<NBLK, NTH, SMEM_BYTES>>>(x, nt, nc, wih, whh, bih, bhh,
                                        wout, bout, wc, bc, out);
}

// round 15
// speedup vs baseline: 1.0794x; 1.0794x over previous
#include <cuda_runtime.h>
#include <math.h>

#define BSZ    65536
#define TT     31
#define HIDN   128
#define NVOCAB 19
#define NCONST 40
#define INSZ   133
#define SLOTS  128
#define NTH    512
#define NW     16
#define NBLK   152

#define OUT_CV  2031616   // BSZ*TT
#define OUT_LP  4063232   // 2*BSZ*TT
#define OUT_TOT 4194304

typedef unsigned long long u64;

// shared float layout
#define S_WHH  0            // float4[kq=32][j=128]
#define S_TOKP 16384        // float4[kq=32][v=32]
#define S_H    20480        // [128][128]
#define S_ACC  36864        // [128][128]
#define S_WX   53248        // [f=9][j=128]
#define S_BSUM 54400
#define S_BTOK 54528
#define S_BCON 54560
#define S_LP   54624        // 128
#define S_NF   54752
// int region
#define SI_POS  0
#define SI_SP   128
#define SI_ACT  256
#define SI_T    384
#define SI_GROW 512
#define SI_STK  640         // 128 x 8
#define SI_LIST 1664        // 128
#define SI_DEAD 1792        // 128
#define SI_CNT  1920        // [0]=A [1]=navail [2]=base [3]=oldc
#define SI_N    1924
#define SMEM_BYTES ((S_NF + SI_N) * 4)

#define FULLM 0xffffffffu

__device__ float g_WihT[INSZ * HIDN];   // [c][j]
__device__ float g_WcT[HIDN * 64];      // [k][c] const head (rarely read)
__device__ int   g_next;

__device__ __forceinline__ u64 ffma2(u64 a, u64 b, u64 c) {
    u64 d;
    asm("fma.rn.f32x2 %0, %1, %2, %3;" : "=l"(d) : "l"(a), "l"(b), "l"(c));
    return d;
}
__device__ __forceinline__ float f2lo(u64 v) { return __uint_as_float((unsigned)v); }
__device__ __forceinline__ float f2hi(u64 v) { return __uint_as_float((unsigned)(v >> 32)); }

__device__ __forceinline__ void lds2(u64& a, u64& b, const float* p) {
    unsigned addr = (unsigned)__cvta_generic_to_shared(p);
    asm("ld.shared.v2.b64 {%0, %1}, [%2];" : "=l"(a), "=l"(b) : "r"(addr));
}

// warp max of f32 via order-preserving s32 map + redux.sync.max.s32 (sm_80+).
__device__ __forceinline__ float rmaxf(float v) {
    int b = __float_as_int(v);
    int k = b ^ ((b >> 31) & 0x7FFFFFFF);
    int r;
    asm("redux.sync.max.s32 %0, %1, 0xffffffff;" : "=r"(r) : "r"(k));
    return __int_as_float(r ^ ((r >> 31) & 0x7FFFFFFF));
}
// warp sum via fixed-point redux.add.s32; SCALE chosen so no overflow.
__device__ __forceinline__ float rsumf(float v, float scale, float inv_scale) {
    int fx = (int)(v * scale);
    int r;
    asm("redux.sync.add.s32 %0, %1, 0xffffffff;" : "=r"(r) : "r"(fx));
    return (float)r * inv_scale;
}

__device__ __forceinline__ float gumbelf(float u) {
    float inner = -logf(u + 1e-9f);
    return -logf(inner + 1e-9f);
}

// GEMV + tanh + h-store for CNT rows (CNT in {2,4}); duplicate rows within one
// call are idempotent (all reads precede all writes).
template<int CNT>
__device__ __forceinline__ void phaseA(float* sm, const int* grp, int lane)
{
    u64 zp[CNT][4];
#pragma unroll
    for (int i = 0; i < CNT; i++)
#pragma unroll
        for (int m = 0; m < 4; m++) zp[i][m] = 0ull;
#pragma unroll 4
    for (int kq = 0; kq < 32; kq++) {
        u64 h01[CNT], h23[CNT];
#pragma unroll
        for (int i = 0; i < CNT; i++)
            lds2(h01[i], h23[i], sm + S_H + grp[i] * HIDN + 4 * kq);
#pragma unroll
        for (int m = 0; m < 4; m++) {
            u64 w01, w23;
            lds2(w01, w23, sm + S_WHH + (kq * 128 + lane + 32 * m) * 4);
#pragma unroll
            for (int i = 0; i < CNT; i++) {
                zp[i][m] = ffma2(h01[i], w01, zp[i][m]);
                zp[i][m] = ffma2(h23[i], w23, zp[i][m]);
            }
        }
    }
    float hnew[CNT][4];
#pragma unroll
    for (int i = 0; i < CNT; i++)
#pragma unroll
        for (int m = 0; m < 4; m++) {
            int j = lane + 32 * m;
            float z = f2lo(zp[i][m]) + f2hi(zp[i][m]);
            float a = sm[S_ACC + grp[i] * HIDN + j];
            hnew[i][m] = tanhf(z + a);
        }
    __syncwarp();
#pragma unroll
    for (int i = 0; i < CNT; i++)
#pragma unroll
        for (int m = 0; m < 4; m++)
            sm[S_H + grp[i] * HIDN + lane + 32 * m] = hnew[i][m];
    __syncwarp();
}

// One decode super-step for up to N rows (real count rcnt <= N; slots beyond
// rcnt duplicate grp[0], gated out of all state writes). nold = count of
// non-fresh rows (prefix) needing the recurrent GEMV. Returns survivor mask.
template<int N>
__device__ __forceinline__ unsigned superstep(float* sm, int* si,
                           const float* __restrict__ noise_tok,
                           const float* __restrict__ noise_c,
                           float* __restrict__ out,
                           const int* grp, int rcnt, int nold, int lane)
{
    int p[N], tt[N], gr[N];
    float g_t[N];
#pragma unroll
    for (int i = 0; i < N; i++) {
        int row = grp[i];
        p[i]  = si[SI_POS + row];
        tt[i] = si[SI_T + row];
        gr[i] = si[SI_GROW + row];
        long long bt = (long long)tt[i] * BSZ + gr[i];
        float u = (lane < NVOCAB) ? __ldg(&noise_tok[bt * NVOCAB + lane]) : 0.5f;
        g_t[i] = gumbelf(u);   // overlaps GEMV below
    }

    // Phase A on the old prefix, in sub-calls of 4/2 with in-call duplicate pad
    if (nold > 0) {
        if (N >= 3 && nold >= 3) {
            if (nold >= 4) { int g4[4] = { grp[0], grp[1], grp[2], grp[3] }; phaseA<4>(sm, g4, lane); }
            else           { int g4[4] = { grp[0], grp[1], grp[2], grp[0] }; phaseA<4>(sm, g4, lane); }
        } else {
            if (nold == 2) { int g2[2] = { grp[0], grp[1] }; phaseA<2>(sm, g2, lane); }
            else           { int g2[2] = { grp[0], grp[0] }; phaseA<2>(sm, g2, lane); }
        }
    }

    // Phase B: token head logits (lane = vocab index), N-way amortized
    u64 tkp[N];
#pragma unroll
    for (int i = 0; i < N; i++) tkp[i] = 0ull;
#pragma unroll 4
    for (int kq = 0; kq < 32; kq++) {
        u64 w01, w23;
        lds2(w01, w23, sm + S_TOKP + (kq * 32 + lane) * 4);
#pragma unroll
        for (int i = 0; i < N; i++) {
            u64 h01, h23;
            lds2(h01, h23, sm + S_H + grp[i] * HIDN + 4 * kq);
            tkp[i] = ffma2(h01, w01, tkp[i]);
            tkp[i] = ffma2(h23, w23, tkp[i]);
        }
    }
    float btok = sm[S_BTOK + lane];
    const float NEGINF = -INFINITY;

    // Phase C1: batched softmax + Gumbel argmax (redux-based, 1-round reductions)
    float ltok[N];
#pragma unroll
    for (int i = 0; i < N; i++) {
        float l = NEGINF;
        if (lane < NVOCAB) {
            l = f2lo(tkp[i]) + f2hi(tkp[i]) + btok;
            if (p[i] >= 15 && lane < 6) l = NEGINF;
        }
        ltok[i] = l;
    }
    float mx[N];
#pragma unroll
    for (int i = 0; i < N; i++) mx[i] = rmaxf(ltok[i]);
    float sme[N];
#pragma unroll
    for (int i = 0; i < N; i++)
        sme[i] = (lane < NVOCAB) ? expf(ltok[i] - mx[i]) : 0.f;
    float ssum[N];
#pragma unroll
    for (int i = 0; i < N; i++)
        ssum[i] = rsumf(sme[i], 33554432.0f, 2.9802322387695312e-8f);
    float lpt[N], sc[N];
#pragma unroll
    for (int i = 0; i < N; i++) {
        float lse = logf(ssum[i]);
        lpt[i] = ltok[i] - mx[i] - lse;
        sc[i]  = lpt[i] + g_t[i];
    }
    float scm[N];
#pragma unroll
    for (int i = 0; i < N; i++) scm[i] = rmaxf(sc[i]);
    int ci[N];
    float lpw[N];
#pragma unroll
    for (int i = 0; i < N; i++) {
        unsigned b = __ballot_sync(FULLM, sc[i] == scm[i]);
        int widx = __ffs(b) - 1;        // first (lowest-index) max = jnp.argmax
        ci[i]  = widx;
        lpw[i] = __shfl_sync(FULLM, lpt[i], widx);
    }

    // Phase C2: rare const head + bookkeeping (only real rows)
    unsigned alive = 0;
#pragma unroll
    for (int i = 0; i < N; i++) {
        if (i >= rcnt) break;
        int row = grp[i];
        int pi  = p[i];
        int choice = ci[i];
        float lp_tok = lpw[i];

        bool is_const = (choice == 18);
        float lp_c = 0.f; int cchoice = 0;
        if (is_const) {   // warp-uniform; W_c lives in global (rare path)
            float2 co = make_float2(0.f, 0.f);
#pragma unroll 8
            for (int k4 = 0; k4 < 32; k4++) {
                float4 hv = *(const float4*)(sm + S_H + row * HIDN + 4 * k4);
#pragma unroll
                for (int b = 0; b < 4; b++) {
                    float2 wc = __ldg((const float2*)(&g_WcT[(4 * k4 + b) * 64 + 2 * lane]));
                    float hk = (b == 0) ? hv.x : (b == 1) ? hv.y : (b == 2) ? hv.z : hv.w;
                    co.x = fmaf(hk, wc.x, co.x);
                    co.y = fmaf(hk, wc.y, co.y);
                }
            }
            long long bt = (long long)tt[i] * BSZ + gr[i];
            float2 uc = make_float2(0.f, 0.f);
            if (lane < 20) uc = *(const float2*)(&noise_c[bt * NCONST + 2 * lane]);
            float bc0 = sm[S_BCON + 2 * lane];
            float bc1 = sm[S_BCON + 2 * lane + 1];
            float la = (lane < 20) ? (co.x + bc0) : NEGINF;
            float lb = (lane < 20) ? (co.y + bc1) : NEGINF;
            float mc   = rmaxf(fmaxf(la, lb));
            float ec   = (lane < 20) ? (expf(la - mc) + expf(lb - mc)) : 0.f;
            float esum = rsumf(ec, 16777216.0f, 5.9604644775390625e-8f);
            float lsec = logf(esum);
            float lpa = la - mc - lsec;
            float lpb = lb - mc - lsec;
            float sa = lpa + gumbelf(uc.x);
            float sb = lpb + gumbelf(uc.y);
            float s_l, lp_l; int i_l;
            if (sb > sa) { s_l = sb; i_l = 2 * lane + 1; lp_l = lpb; }
            else         { s_l = sa; i_l = 2 * lane;     lp_l = lpa; }
            float m2 = rmaxf(s_l);
            unsigned b2 = __ballot_sync(FULLM, s_l == m2);
            int wl = __ffs(b2) - 1;     // lowest lane among maxes = lowest index
            cchoice = __shfl_sync(FULLM, i_l, wl);
            lp_c    = __shfl_sync(FULLM, lp_l, wl);
        }

        if (lane == 0) {
            float lpn = sm[S_LP + row] + lp_tok + (is_const ? lp_c : 0.f);
            out[gr[i] * TT + pi] = (float)choice;
            if (is_const) out[OUT_CV + gr[i] * TT + pi] = -10.f + 0.5f * (float)cchoice;
            int arity = (choice < 4) ? 2 : ((choice < 6) ? 1 : 0);
            int sp = si[SI_SP + row];
            if (arity == 2) {
                int wsp = sp < 7 ? sp : 7;
                si[SI_STK + row * 8 + wsp] = 2 * pi + 2;
            }
            int sp1 = sp + (arity == 2 ? 1 : 0);
            int nxt, sp2;
            if (arity != 0) { nxt = 2 * pi + 1; sp2 = sp1; }
            else {
                int ridx = sp1 - 1; if (ridx < 0) ridx = 0; if (ridx > 7) ridx = 7;
                nxt = (sp1 > 0) ? si[SI_STK + row * 8 + ridx] : -1;
                sp2 = (sp1 > 0) ? sp1 - 1 : 0;
            }
            if (nxt > TT - 1) nxt = -1;
            if (nxt >= 0) {
                alive |= (1u << i);
                sm[S_LP + row]   = lpn;
                si[SI_POS + row] = nxt;
                si[SI_SP + row]  = sp2;
                si[SI_T + row]   = tt[i] + 1;
            } else {
                si[SI_ACT + row] = 0;
                out[OUT_LP + gr[i]] = lpn;
            }
        }
        if (choice & 15) {
            int cb = 4 * pi;
#pragma unroll
            for (int m = 0; m < 4; m++) {
                int j = lane + 32 * m;
                float a = sm[S_ACC + row * HIDN + j];
#pragma unroll
                for (int b = 0; b < 4; b++)
                    if (choice & (1 << b))
                        a += __ldg(&g_WihT[(cb + b) * HIDN + j]);
                sm[S_ACC + row * HIDN + j] = a;
            }
        }
    }
    alive = __shfl_sync(FULLM, alive, 0);
    __syncwarp();
    return alive;
}

__device__ __forceinline__ unsigned run_n(int n, int nol, float* sm, int* si,
        const float* nt, const float* nc, float* out, const int* grp, int lane)
{
    if (n > 2) return superstep<4>(sm, si, nt, nc, out, grp, n, nol, lane);
    else       return superstep<2>(sm, si, nt, nc, out, grp, n, nol, lane);
}

__global__ void __launch_bounds__(NTH, 1)
rnn_main(const float* __restrict__ x,
         const float* __restrict__ noise_tok,
         const float* __restrict__ noise_c,
         const float* __restrict__ W_ih,
         const float* __restrict__ W_hh,
         const float* __restrict__ b_ih,
         const float* __restrict__ b_hh,
         const float* __restrict__ W_out,
         const float* __restrict__ b_out,
         const float* __restrict__ W_c,
         const float* __restrict__ b_c,
         float* __restrict__ out)
{
    extern __shared__ float sm[];
    int* si = (int*)(sm + S_NF);
    int tid = threadIdx.x;
    int w = tid >> 5, lane = tid & 31;

    // ---- stage weights ----
    {
        const float4* src = (const float4*)W_hh;   // [j][32]
        float4* dst = (float4*)(sm + S_WHH);
        for (int idx = tid; idx < 32 * 128; idx += NTH) {
            int kq = idx >> 7, j = idx & 127;
            dst[kq * 128 + j] = src[j * 32 + kq];
        }
    }
    {
        float4* dst = (float4*)(sm + S_TOKP);
        const float4 z4 = make_float4(0.f, 0.f, 0.f, 0.f);
        const float4* src = (const float4*)W_out;  // [v][32]
        for (int idx = tid; idx < 32 * 32; idx += NTH) {
            int kq = idx >> 5, v = idx & 31;
            dst[kq * 32 + v] = (v < NVOCAB) ? src[v * 32 + kq] : z4;
        }
    }
    for (int idx = tid; idx < 9 * HIDN; idx += NTH) {
        int f = idx >> 7, j = idx & 127;
        sm[S_WX + f * 128 + j] = W_ih[j * INSZ + 124 + f];
    }
    if (tid < HIDN) sm[S_BSUM + tid] = b_ih[tid] + b_hh[tid];
    if (tid < 32) sm[S_BTOK + tid] = (tid < NVOCAB) ? b_out[tid] : 0.f;
    if (tid < 64) sm[S_BCON + tid] = (tid < NCONST) ? b_c[tid] : 0.f;
    if (tid < SLOTS) si[SI_ACT + tid] = 0;
    __syncthreads();

    // ---- persistent work loop (2 barriers per round) ----
    for (;;) {
        if (w == 0) {
            unsigned lt = (1u << lane) - 1u;
            int nold = 0, ndead = 0;
            unsigned am[4];
            int po[4], pd[4];
#pragma unroll
            for (int c = 0; c < 4; c++) {
                int act = si[SI_ACT + 32 * c + lane];
                unsigned m = __ballot_sync(FULLM, act != 0);
                am[c] = m; po[c] = nold; pd[c] = ndead;
                nold  += __popc(m);
                ndead += 32 - __popc(m);
            }
            int base = 0;
            if (lane == 0 && ndead > 0) base = atomicAdd(&g_next, ndead);
            base = __shfl_sync(FULLM, base, 0);
            int navail = BSZ - base;
            if (navail < 0) navail = 0;
            if (navail > ndead) navail = ndead;
#pragma unroll
            for (int c = 0; c < 4; c++) {
                int slot = 32 * c + lane;
                if ((am[c] >> lane) & 1) si[SI_LIST + po[c] + __popc(am[c] & lt)] = slot;
                else                     si[SI_DEAD + pd[c] + __popc(~am[c] & lt)] = slot;
            }
            __syncwarp();
            for (int q = lane; q < navail; q += 32)
                si[SI_LIST + nold + q] = si[SI_DEAD + q];
            if (lane == 0) {
                si[SI_CNT]     = nold + navail;
                si[SI_CNT + 1] = navail;
                si[SI_CNT + 2] = (ndead > 0) ? base : 0;
                si[SI_CNT + 3] = nold;
            }
        }
        __syncthreads();
        int A = si[SI_CNT];
        int navail = si[SI_CNT + 1];
        int rbase  = si[SI_CNT + 2];
        int oldc   = si[SI_CNT + 3];
        if (A == 0) break;
        bool drain = (navail == 0) && (rbase >= BSZ);   // pool empty forever

        // this warp's contiguous chunk of the active list
        int lo = (A * w) / NW;
        int hi = (A * (w + 1)) / NW;

        // owner-refill: init this warp's fresh rows (h = tanh(acc); step-0 GEMV = 0)
        int fstart = lo > oldc ? lo : oldc;
        for (int idx = fstart; idx < hi; idx++) {
            int slot = si[SI_LIST + idx];
            int gr = rbase + (idx - oldc);
            float xv[9];
#pragma unroll
            for (int f = 0; f < 9; f++) xv[f] = __ldg(&x[gr * 9 + f]);
#pragma unroll
            for (int m = 0; m < 4; m++) {
                int j = lane + 32 * m;
                float a = sm[S_BSUM + j];
#pragma unroll
                for (int f = 0; f < 9; f++) a = fmaf(xv[f], sm[S_WX + f * 128 + j], a);
                sm[S_ACC + slot * HIDN + j] = a;
                sm[S_H + slot * HIDN + j] = tanhf(a);
            }
            // default-init this row's output slice (each row refilled exactly once)
            if (lane < TT) {
                out[gr * TT + lane] = -1.f;
                out[OUT_CV + gr * TT + lane] = 0.f;
            }
            if (lane == 0) {
                si[SI_POS + slot]  = 0;
                si[SI_SP + slot]   = 0;
                si[SI_T + slot]    = 0;
                si[SI_ACT + slot]  = 1;
                si[SI_GROW + slot] = gr;
                sm[S_LP + slot]    = 0.f;
            }
        }
        __syncwarp();

        // super-steps of up to 4 rows (chunks of 8 -> two fully-amortized calls)
        for (int base = lo; base < hi; base += 4) {
            int n = hi - base; if (n > 4) n = 4;
            int grp[4];
#pragma unroll
            for (int q = 0; q < 4; q++)
                grp[q] = si[SI_LIST + base + (q < n ? q : 0)];
            int nol = oldc - base;
            if (nol < 0) nol = 0;
            if (nol > n) nol = n;
            unsigned mv = run_n(n, nol, sm, si, noise_tok, noise_c, out, grp, lane);

            // drain mode: run this chunk's survivors to completion, no barriers
            while (drain && mv) {
                int ag[4]; int cnt = 0;
                for (int q = 0; q < n; q++)
                    if ((mv >> q) & 1) ag[cnt++] = grp[q];
                n = cnt;
                for (int q = 0; q < 4; q++) grp[q] = ag[q < n ? q : 0];
                mv = run_n(n, n, sm, si, noise_tok, noise_c, out, grp, lane);
            }
        }
        __syncthreads();
        if (drain) break;   // all remaining rows ran to completion above
    }
}

// prep only (out-init handled per-row at refill time)
__global__ void setup_kernel(const float* __restrict__ W_ih, const float* __restrict__ W_c)
{
    int i = blockIdx.x * blockDim.x + threadIdx.x;
    if (i == 0) g_next = 0;
    if (i < INSZ * HIDN) {
        int c = i / HIDN, j = i % HIDN;
        g_WihT[c * HIDN + j] = W_ih[j * INSZ + c];
    }
    if (i < HIDN * 64) {
        int k = i >> 6, c = i & 63;
        g_WcT[k * 64 + c] = (c < NCONST) ? W_c[c * HIDN + k] : 0.f;
    }
}

extern "C" void kernel_launch(void* const* d_in, const int* in_sizes, int n_in,
                              void* d_out, int out_size)
{
    const float* x    = (const float*)d_in[0];
    const float* nt   = (const float*)d_in[1];
    const float* nc   = (const float*)d_in[2];
    const float* wih  = (const float*)d_in[3];
    const float* whh  = (const float*)d_in[4];
    const float* bih  = (const float*)d_in[5];
    const float* bhh  = (const float*)d_in[6];
    const float* wout = (const float*)d_in[7];
    const float* bout = (const float*)d_in[8];
    const float* wc   = (const float*)d_in[9];
    const float* bc   = (const float*)d_in[10];
    float* out = (float*)d_out;

    cudaFuncSetAttribute((const void*)rnn_main,
                         cudaFuncAttributeMaxDynamicSharedMemorySize, SMEM_BYTES);
    setup_kernel<<<(INSZ * HIDN + 255) / 256, 256>>>(wih, wc);
    rnn_main<<<NBLK, NTH, SMEM_BYTES>>>(x, nt, nc, wih, whh, bih, bhh,
                                        wout, bout, wc, bc, out);
}

// round 16
// speedup vs baseline: 1.1027x; 1.0216x over previous
#include <cuda_runtime.h>
#include <math.h>

#define BSZ    65536
#define TT     31
#define HIDN   128
#define NVOCAB 19
#define NCONST 40
#define INSZ   133
#define SLOTS  96
#define NTH    512
#define NBLK   152

#define OUT_CV  2031616   // BSZ*TT
#define OUT_LP  4063232   // 2*BSZ*TT
#define OUT_TOT 4194304

typedef unsigned long long u64;

// shared float layout
#define S_WHH  0            // float4[kq=32][j=128]
#define S_TOKP 16384        // float4[kq=32][v=32]
#define S_CON  20480        // [k][64]
#define S_H    28672        // [96][128]
#define S_ACC  40960        // [96][128]
#define S_WX   53248        // [f=9][j=128]
#define S_BSUM 54400
#define S_BTOK 54528
#define S_BCON 54560
#define S_LP   54624        // 96
#define S_NF   54720
// int region
#define SI_POS  0
#define SI_SP   96
#define SI_ACT  192
#define SI_T    288
#define SI_GROW 384
#define SI_STK  480         // 96 x 8
#define SI_LIST 1248        // 96
#define SI_DEAD 1344        // 96
#define SI_CNT  1440        // [0]=A [1]=navail [2]=base [3]=oldc
#define SI_N    1444
#define SMEM_BYTES ((S_NF + SI_N) * 4)

#define FULLM 0xffffffffu

__device__ float g_WihT[INSZ * HIDN];   // [c][j]
__device__ int   g_next;

__device__ __forceinline__ u64 ffma2(u64 a, u64 b, u64 c) {
    u64 d;
    asm("fma.rn.f32x2 %0, %1, %2, %3;" : "=l"(d) : "l"(a), "l"(b), "l"(c));
    return d;
}
__device__ __forceinline__ float f2lo(u64 v) { return __uint_as_float((unsigned)v); }
__device__ __forceinline__ float f2hi(u64 v) { return __uint_as_float((unsigned)(v >> 32)); }

__device__ __forceinline__ void lds2(u64& a, u64& b, const float* p) {
    unsigned addr = (unsigned)__cvta_generic_to_shared(p);
    asm("ld.shared.v2.b64 {%0, %1}, [%2];" : "=l"(a), "=l"(b) : "r"(addr));
}

// warp max of f32 via order-preserving s32 map + redux.sync.max.s32 (sm_80+).
__device__ __forceinline__ float rmaxf(float v) {
    int b = __float_as_int(v);
    int k = b ^ ((b >> 31) & 0x7FFFFFFF);
    int r;
    asm("redux.sync.max.s32 %0, %1, 0xffffffff;" : "=r"(r) : "r"(k));
    return __int_as_float(r ^ ((r >> 31) & 0x7FFFFFFF));
}
// warp sum via fixed-point redux.add.s32; SCALE chosen so no overflow.
__device__ __forceinline__ float rsumf(float v, float scale, float inv_scale) {
    int fx = (int)(v * scale);
    int r;
    asm("redux.sync.add.s32 %0, %1, 0xffffffff;" : "=r"(r) : "r"(fx));
    return (float)r * inv_scale;
}

__device__ __forceinline__ float gumbelf(float u) {
    float inner = -logf(u + 1e-9f);
    return -logf(inner + 1e-9f);
}

// GEMV + tanh + h-store for CNT rows (CNT in {2,4}); duplicate rows within one
// call are idempotent (all reads precede all writes). ACC preloaded up front so
// its 29-cyc LDS latency hides under the GEMV instead of feeding tanh directly.
template<int CNT>
__device__ __forceinline__ void phaseA(float* sm, const int* grp, int lane)
{
    float af[CNT][4];
#pragma unroll
    for (int i = 0; i < CNT; i++)
#pragma unroll
        for (int m = 0; m < 4; m++)
            af[i][m] = sm[S_ACC + grp[i] * HIDN + lane + 32 * m];

    u64 zp[CNT][4];
#pragma unroll
    for (int i = 0; i < CNT; i++)
#pragma unroll
        for (int m = 0; m < 4; m++) zp[i][m] = 0ull;
#pragma unroll 8
    for (int kq = 0; kq < 32; kq++) {
        u64 h01[CNT], h23[CNT];
#pragma unroll
        for (int i = 0; i < CNT; i++)
            lds2(h01[i], h23[i], sm + S_H + grp[i] * HIDN + 4 * kq);
#pragma unroll
        for (int m = 0; m < 4; m++) {
            u64 w01, w23;
            lds2(w01, w23, sm + S_WHH + (kq * 128 + lane + 32 * m) * 4);
#pragma unroll
            for (int i = 0; i < CNT; i++) {
                zp[i][m] = ffma2(h01[i], w01, zp[i][m]);
                zp[i][m] = ffma2(h23[i], w23, zp[i][m]);
            }
        }
    }
    float hnew[CNT][4];
#pragma unroll
    for (int i = 0; i < CNT; i++)
#pragma unroll
        for (int m = 0; m < 4; m++) {
            float z = f2lo(zp[i][m]) + f2hi(zp[i][m]);
            hnew[i][m] = tanhf(z + af[i][m]);
        }
    __syncwarp();
#pragma unroll
    for (int i = 0; i < CNT; i++)
#pragma unroll
        for (int m = 0; m < 4; m++)
            sm[S_H + grp[i] * HIDN + lane + 32 * m] = hnew[i][m];
    __syncwarp();
}

// One decode super-step for up to N rows (real count rcnt <= N; slots beyond
// rcnt duplicate grp[0], gated out of all state writes). nold = count of
// non-fresh rows (prefix) needing the recurrent GEMV. Returns survivor mask.
template<int N>
__device__ __forceinline__ unsigned superstep(float* sm, int* si,
                           const float* __restrict__ noise_tok,
                           const float* __restrict__ noise_c,
                           float* __restrict__ out,
                           const int* grp, int rcnt, int nold, int lane)
{
    int p[N], tt[N], gr[N];
    float g_t[N];
#pragma unroll
    for (int i = 0; i < N; i++) {
        int row = grp[i];
        p[i]  = si[SI_POS + row];
        tt[i] = si[SI_T + row];
        gr[i] = si[SI_GROW + row];
        long long bt = (long long)tt[i] * BSZ + gr[i];
        float u = (lane < NVOCAB) ? __ldg(&noise_tok[bt * NVOCAB + lane]) : 0.5f;
        g_t[i] = gumbelf(u);   // overlaps GEMV below
    }

    // Phase A on the old prefix, in sub-calls of 4/2 with in-call duplicate pad
    if (nold > 0) {
        if (N >= 5 && nold >= 5) {
            { int g4[4] = { grp[0], grp[1], grp[2], grp[3] }; phaseA<4>(sm, g4, lane); }
            if (nold == 6) { int g2[2] = { grp[4], grp[5] }; phaseA<2>(sm, g2, lane); }
            else           { int g2[2] = { grp[4], grp[4] }; phaseA<2>(sm, g2, lane); }
        } else if (N >= 3 && nold >= 3) {
            if (nold >= 4) { int g4[4] = { grp[0], grp[1], grp[2], grp[3] }; phaseA<4>(sm, g4, lane); }
            else           { int g4[4] = { grp[0], grp[1], grp[2], grp[0] }; phaseA<4>(sm, g4, lane); }
        } else {
            if (nold == 2) { int g2[2] = { grp[0], grp[1] }; phaseA<2>(sm, g2, lane); }
            else           { int g2[2] = { grp[0], grp[0] }; phaseA<2>(sm, g2, lane); }
        }
    }

    // Phase B: token head logits (lane = vocab index), N-way amortized
    u64 tkp[N];
#pragma unroll
    for (int i = 0; i < N; i++) tkp[i] = 0ull;
#pragma unroll 8
    for (int kq = 0; kq < 32; kq++) {
        u64 w01, w23;
        lds2(w01, w23, sm + S_TOKP + (kq * 32 + lane) * 4);
#pragma unroll
        for (int i = 0; i < N; i++) {
            u64 h01, h23;
            lds2(h01, h23, sm + S_H + grp[i] * HIDN + 4 * kq);
            tkp[i] = ffma2(h01, w01, tkp[i]);
            tkp[i] = ffma2(h23, w23, tkp[i]);
        }
    }
    float btok = sm[S_BTOK + lane];
    const float NEGINF = -INFINITY;

    // Phase C1: batched softmax + Gumbel argmax (redux-based, 1-round reductions)
    float ltok[N];
#pragma unroll
    for (int i = 0; i < N; i++) {
        float l = NEGINF;
        if (lane < NVOCAB) {
            l = f2lo(tkp[i]) + f2hi(tkp[i]) + btok;
            if (p[i] >= 15 && lane < 6) l = NEGINF;
        }
        ltok[i] = l;
    }
    float mx[N];
#pragma unroll
    for (int i = 0; i < N; i++) mx[i] = rmaxf(ltok[i]);
    float sme[N];
#pragma unroll
    for (int i = 0; i < N; i++)
        sme[i] = (lane < NVOCAB) ? expf(ltok[i] - mx[i]) : 0.f;
    float ssum[N];
#pragma unroll
    for (int i = 0; i < N; i++)
        ssum[i] = rsumf(sme[i], 33554432.0f, 2.9802322387695312e-8f);
    float lpt[N], sc[N];
#pragma unroll
    for (int i = 0; i < N; i++) {
        float lse = logf(ssum[i]);
        lpt[i] = ltok[i] - mx[i] - lse;
        sc[i]  = lpt[i] + g_t[i];
    }
    float scm[N];
#pragma unroll
    for (int i = 0; i < N; i++) scm[i] = rmaxf(sc[i]);
    int ci[N];
    float lpw[N];
#pragma unroll
    for (int i = 0; i < N; i++) {
        unsigned b = __ballot_sync(FULLM, sc[i] == scm[i]);
        int widx = __ffs(b) - 1;        // first (lowest-index) max = jnp.argmax
        ci[i]  = widx;
        lpw[i] = __shfl_sync(FULLM, lpt[i], widx);
    }

    // Phase C2: rare const head + bookkeeping (only real rows)
    unsigned alive = 0;
#pragma unroll
    for (int i = 0; i < N; i++) {
        if (i >= rcnt) break;
        int row = grp[i];
        int pi  = p[i];
        int choice = ci[i];
        float lp_tok = lpw[i];

        bool is_const = (choice == 18);
        float lp_c = 0.f; int cchoice = 0;
        if (is_const) {   // warp-uniform
            float2 co = make_float2(0.f, 0.f);
#pragma unroll 8
            for (int k4 = 0; k4 < 32; k4++) {
                float4 hv = *(const float4*)(sm + S_H + row * HIDN + 4 * k4);
#pragma unroll
                for (int b = 0; b < 4; b++) {
                    float2 wc = *(const float2*)(sm + S_CON + (4 * k4 + b) * 64 + 2 * lane);
                    float hk = (b == 0) ? hv.x : (b == 1) ? hv.y : (b == 2) ? hv.z : hv.w;
                    co.x = fmaf(hk, wc.x, co.x);
                    co.y = fmaf(hk, wc.y, co.y);
                }
            }
            long long bt = (long long)tt[i] * BSZ + gr[i];
            float2 uc = make_float2(0.f, 0.f);
            if (lane < 20) uc = *(const float2*)(&noise_c[bt * NCONST + 2 * lane]);
            float bc0 = sm[S_BCON + 2 * lane];
            float bc1 = sm[S_BCON + 2 * lane + 1];
            float la = (lane < 20) ? (co.x + bc0) : NEGINF;
            float lb = (lane < 20) ? (co.y + bc1) : NEGINF;
            float mc   = rmaxf(fmaxf(la, lb));
            float ec   = (lane < 20) ? (expf(la - mc) + expf(lb - mc)) : 0.f;
            float esum = rsumf(ec, 16777216.0f, 5.9604644775390625e-8f);
            float lsec = logf(esum);
            float lpa = la - mc - lsec;
            float lpb = lb - mc - lsec;
            float sa = lpa + gumbelf(uc.x);
            float sb = lpb + gumbelf(uc.y);
            float s_l, lp_l; int i_l;
            if (sb > sa) { s_l = sb; i_l = 2 * lane + 1; lp_l = lpb; }
            else         { s_l = sa; i_l = 2 * lane;     lp_l = lpa; }
            float m2 = rmaxf(s_l);
            unsigned b2 = __ballot_sync(FULLM, s_l == m2);
            int wl = __ffs(b2) - 1;     // lowest lane among maxes = lowest index
            cchoice = __shfl_sync(FULLM, i_l, wl);
            lp_c    = __shfl_sync(FULLM, lp_l, wl);
        }

        if (lane == 0) {
            float lpn = sm[S_LP + row] + lp_tok + (is_const ? lp_c : 0.f);
            out[gr[i] * TT + pi] = (float)choice;
            if (is_const) out[OUT_CV + gr[i] * TT + pi] = -10.f + 0.5f * (float)cchoice;
            int arity = (choice < 4) ? 2 : ((choice < 6) ? 1 : 0);
            int sp = si[SI_SP + row];
            if (arity == 2) {
                int wsp = sp < 7 ? sp : 7;
                si[SI_STK + row * 8 + wsp] = 2 * pi + 2;
            }
            int sp1 = sp + (arity == 2 ? 1 : 0);
            int nxt, sp2;
            if (arity != 0) { nxt = 2 * pi + 1; sp2 = sp1; }
            else {
                int ridx = sp1 - 1; if (ridx < 0) ridx = 0; if (ridx > 7) ridx = 7;
                nxt = (sp1 > 0) ? si[SI_STK + row * 8 + ridx] : -1;
                sp2 = (sp1 > 0) ? sp1 - 1 : 0;
            }
            if (nxt > TT - 1) nxt = -1;
            if (nxt >= 0) {
                alive |= (1u << i);
                sm[S_LP + row]   = lpn;
                si[SI_POS + row] = nxt;
                si[SI_SP + row]  = sp2;
                si[SI_T + row]   = tt[i] + 1;
            } else {
                si[SI_ACT + row] = 0;
                out[OUT_LP + gr[i]] = lpn;
            }
        }
        if (choice & 15) {
            int cb = 4 * pi;
#pragma unroll
            for (int m = 0; m < 4; m++) {
                int j = lane + 32 * m;
                float a = sm[S_ACC + row * HIDN + j];
#pragma unroll
                for (int b = 0; b < 4; b++)
                    if (choice & (1 << b))
                        a += __ldg(&g_WihT[(cb + b) * HIDN + j]);
                sm[S_ACC + row * HIDN + j] = a;
            }
        }
    }
    alive = __shfl_sync(FULLM, alive, 0);
    __syncwarp();
    return alive;
}

__device__ __forceinline__ unsigned run_n(int n, int nol, float* sm, int* si,
        const float* nt, const float* nc, float* out, const int* grp, int lane)
{
    if (n > 4)      return superstep<6>(sm, si, nt, nc, out, grp, n, nol, lane);
    else if (n > 2) return superstep<4>(sm, si, nt, nc, out, grp, n, nol, lane);
    else            return superstep<2>(sm, si, nt, nc, out, grp, n, nol, lane);
}

__global__ void __launch_bounds__(NTH, 1)
rnn_main(const float* __restrict__ x,
         const float* __restrict__ noise_tok,
         const float* __restrict__ noise_c,
         const float* __restrict__ W_ih,
         const float* __restrict__ W_hh,
         const float* __restrict__ b_ih,
         const float* __restrict__ b_hh,
         const float* __restrict__ W_out,
         const float* __restrict__ b_out,
         const float* __restrict__ W_c,
         const float* __restrict__ b_c,
         float* __restrict__ out)
{
    extern __shared__ float sm[];
    int* si = (int*)(sm + S_NF);
    int tid = threadIdx.x;
    int w = tid >> 5, lane = tid & 31;

    // ---- stage weights ----
    {
        const float4* src = (const float4*)W_hh;   // [j][32]
        float4* dst = (float4*)(sm + S_WHH);
        for (int idx = tid; idx < 32 * 128; idx += NTH) {
            int kq = idx >> 7, j = idx & 127;
            dst[kq * 128 + j] = src[j * 32 + kq];
        }
    }
    {
        float4* dst = (float4*)(sm + S_TOKP);
        const float4 z4 = make_float4(0.f, 0.f, 0.f, 0.f);
        const float4* src = (const float4*)W_out;  // [v][32]
        for (int idx = tid; idx < 32 * 32; idx += NTH) {
            int kq = idx >> 5, v = idx & 31;
            dst[kq * 32 + v] = (v < NVOCAB) ? src[v * 32 + kq] : z4;
        }
    }
    for (int idx = tid; idx < HIDN * 64; idx += NTH) sm[S_CON + idx] = 0.f;
    __syncthreads();
    for (int idx = tid; idx < NCONST * HIDN; idx += NTH) {
        int c = idx / HIDN, k = idx % HIDN;
        sm[S_CON + k * 64 + c] = W_c[idx];
    }
    for (int idx = tid; idx < 9 * HIDN; idx += NTH) {
        int f = idx >> 7, j = idx & 127;
        sm[S_WX + f * 128 + j] = W_ih[j * INSZ + 124 + f];
    }
    if (tid < HIDN) sm[S_BSUM + tid] = b_ih[tid] + b_hh[tid];
    if (tid < 32) sm[S_BTOK + tid] = (tid < NVOCAB) ? b_out[tid] : 0.f;
    if (tid < 64) sm[S_BCON + tid] = (tid < NCONST) ? b_c[tid] : 0.f;
    if (tid < SLOTS) si[SI_ACT + tid] = 0;
    __syncthreads();

    // ---- persistent work loop (2 barriers per round) ----
    for (;;) {
        if (w == 0) {
            unsigned lt = (1u << lane) - 1u;
            int nold = 0, ndead = 0;
            unsigned am[3];
            int po[3], pd[3];
#pragma unroll
            for (int c = 0; c < 3; c++) {
                int act = si[SI_ACT + 32 * c + lane];
                unsigned m = __ballot_sync(FULLM, act != 0);
                am[c] = m; po[c] = nold; pd[c] = ndead;
                nold  += __popc(m);
                ndead += 32 - __popc(m);
            }
            int base = 0;
            if (lane == 0 && ndead > 0) base = atomicAdd(&g_next, ndead);
            base = __shfl_sync(FULLM, base, 0);
            int navail = BSZ - base;
            if (navail < 0) navail = 0;
            if (navail > ndead) navail = ndead;
#pragma unroll
            for (int c = 0; c < 3; c++) {
                int slot = 32 * c + lane;
                if ((am[c] >> lane) & 1) si[SI_LIST + po[c] + __popc(am[c] & lt)] = slot;
                else                     si[SI_DEAD + pd[c] + __popc(~am[c] & lt)] = slot;
            }
            __syncwarp();
            for (int q = lane; q < navail; q += 32)
                si[SI_LIST + nold + q] = si[SI_DEAD + q];
            if (lane == 0) {
                si[SI_CNT]     = nold + navail;
                si[SI_CNT + 1] = navail;
                si[SI_CNT + 2] = (ndead > 0) ? base : 0;
                si[SI_CNT + 3] = nold;
            }
        }
        __syncthreads();
        int A = si[SI_CNT];
        int navail = si[SI_CNT + 1];
        int rbase  = si[SI_CNT + 2];
        int oldc   = si[SI_CNT + 3];
        if (A == 0) break;
        bool drain = (navail == 0) && (rbase >= BSZ);   // pool empty forever

        // this warp's contiguous chunk of the active list
        int lo = (A * w) >> 4;
        int hi = (A * (w + 1)) >> 4;

        // owner-refill: init this warp's fresh rows (h = tanh(acc); step-0 GEMV = 0)
        int fstart = lo > oldc ? lo : oldc;
        for (int idx = fstart; idx < hi; idx++) {
            int slot = si[SI_LIST + idx];
            int gr = rbase + (idx - oldc);
            float xv[9];
#pragma unroll
            for (int f = 0; f < 9; f++) xv[f] = __ldg(&x[gr * 9 + f]);
#pragma unroll
            for (int m = 0; m < 4; m++) {
                int j = lane + 32 * m;
                float a = sm[S_BSUM + j];
#pragma unroll
                for (int f = 0; f < 9; f++) a = fmaf(xv[f], sm[S_WX + f * 128 + j], a);
                sm[S_ACC + slot * HIDN + j] = a;
                sm[S_H + slot * HIDN + j] = tanhf(a);
            }
            // default-init this row's output slice (each row refilled exactly once)
            if (lane < TT) {
                out[gr * TT + lane] = -1.f;
                out[OUT_CV + gr * TT + lane] = 0.f;
            }
            if (lane == 0) {
                si[SI_POS + slot]  = 0;
                si[SI_SP + slot]   = 0;
                si[SI_T + slot]    = 0;
                si[SI_ACT + slot]  = 1;
                si[SI_GROW + slot] = gr;
                sm[S_LP + slot]    = 0.f;
            }
        }
        __syncwarp();

        // super-steps of up to 6 rows
        for (int base = lo; base < hi; base += 6) {
            int n = hi - base; if (n > 6) n = 6;
            int grp[6];
#pragma unroll
            for (int q = 0; q < 6; q++)
                grp[q] = si[SI_LIST + base + (q < n ? q : 0)];
            int nol = oldc - base;
            if (nol < 0) nol = 0;
            if (nol > n) nol = n;
            unsigned mv = run_n(n, nol, sm, si, noise_tok, noise_c, out, grp, lane);

            // drain mode: run this chunk's survivors to completion, no barriers
            while (drain && mv) {
                int ag[6]; int cnt = 0;
                for (int q = 0; q < n; q++)
                    if ((mv >> q) & 1) ag[cnt++] = grp[q];
                n = cnt;
                for (int q = 0; q < 6; q++) grp[q] = ag[q < n ? q : 0];
                mv = run_n(n, n, sm, si, noise_tok, noise_c, out, grp, lane);
            }
        }
        __syncthreads();
        if (drain) break;   // all remaining rows ran to completion above
    }
}

// prep only (out-init handled per-row at refill time)
__global__ void setup_kernel(const float* __restrict__ W_ih)
{
    int i = blockIdx.x * blockDim.x + threadIdx.x;
    if (i == 0) g_next = 0;
    if (i < INSZ * HIDN) {
        int c = i / HIDN, j = i % HIDN;
        g_WihT[c * HIDN + j] = W_ih[j * INSZ + c];
    }
}

extern "C" void kernel_launch(void* const* d_in, const int* in_sizes, int n_in,
                              void* d_out, int out_size)
{
    const float* x    = (const float*)d_in[0];
    const float* nt   = (const float*)d_in[1];
    const float* nc   = (const float*)d_in[2];
    const float* wih  = (const float*)d_in[3];
    const float* whh  = (const float*)d_in[4];
    const float* bih  = (const float*)d_in[5];
    const float* bhh  = (const float*)d_in[6];
    const float* wout = (const float*)d_in[7];
    const float* bout = (const float*)d_in[8];
    const float* wc   = (const float*)d_in[9];
    const float* bc   = (const float*)d_in[10];
    float* out = (float*)d_out;

    cudaFuncSetAttribute((const void*)rnn_main,
                         cudaFuncAttributeMaxDynamicSharedMemorySize, SMEM_BYTES);
    setup_kernel<<<(INSZ * HIDN + 255) / 256, 256>>>(wih);
    rnn_main<<<NBLK, NTH, SMEM_BYTES>>>(x, nt, nc, wih, whh, bih, bhh,
                                        wout, bout, wc, bc, out);
}